// round 17
// baseline (speedup 1.0000x reference)
#include <cuda_runtime.h>
#include <cuda_fp16.h>
#include <cstdint>
#include <math.h>

// Problem constants
#define T_TOK 1024
#define H_DIM 1024
#define I_DIM 512
#define N_EXP 16
#define TOPK  4
#define NPAIR (T_TOK * TOPK)   // 4096

// ============================================================================
// Scratch (__device__ globals; allocations are forbidden)
// ============================================================================
__device__ int   g_offset[N_EXP + 1];
__device__ int   g_tok[NPAIR];
__device__ float g_wt[NPAIR];

__device__ __half g_Xh[T_TOK * H_DIM];               // hidden, fp16
__device__ __half g_GUh[N_EXP * 2 * I_DIM * H_DIM];  // gate_up, fp16
__device__ __half g_Dh[N_EXP * H_DIM * I_DIM];       // down, fp16
__device__ __half g_Hh[NPAIR * I_DIM];               // silu(g)*u, fp16

// ============================================================================
// PTX helpers (sm_80/sm_90 baseline features — legal on plain compute_103)
// ============================================================================
__device__ __forceinline__ uint32_t smem_to_u32(const void* p) {
    uint32_t a;
    asm("{ .reg .u64 t; cvta.to.shared.u64 t, %1; cvt.u32.u64 %0, t; }" : "=r"(a) : "l"(p));
    return a;
}
__device__ __forceinline__ void cp16(uint32_t saddr, const void* g, int szbytes) {
    asm volatile("cp.async.cg.shared.global [%0], [%1], 16, %2;"
                 :: "r"(saddr), "l"(g), "r"(szbytes) : "memory");
}
#define CP_COMMIT() asm volatile("cp.async.commit_group;" ::: "memory")
#define CP_WAIT1()  asm volatile("cp.async.wait_group 1;" ::: "memory")
#define CP_WAIT2()  asm volatile("cp.async.wait_group 2;" ::: "memory")

__device__ __forceinline__ void ldsm_x4(uint32_t* r, uint32_t addr) {
    asm volatile("ldmatrix.sync.aligned.m8n8.x4.shared.b16 {%0,%1,%2,%3}, [%4];"
                 : "=r"(r[0]), "=r"(r[1]), "=r"(r[2]), "=r"(r[3]) : "r"(addr));
}
__device__ __forceinline__ void mma16816(float* c, const uint32_t* a, uint32_t b0, uint32_t b1) {
    asm volatile(
        "mma.sync.aligned.m16n8k16.row.col.f32.f16.f16.f32 "
        "{%0,%1,%2,%3}, {%4,%5,%6,%7}, {%8,%9}, {%0,%1,%2,%3};"
        : "+f"(c[0]), "+f"(c[1]), "+f"(c[2]), "+f"(c[3])
        : "r"(a[0]), "r"(a[1]), "r"(a[2]), "r"(a[3]), "r"(b0), "r"(b1));
}
__device__ __forceinline__ void red_add_v2(float* gptr, float a, float b) {
    asm volatile("red.global.add.v2.f32 [%0], {%1, %2};"
                 :: "l"(gptr), "f"(a), "f"(b) : "memory");
}

// Tile smem rows are 64B (32 fp16), 4x16B chunks, chunk' = chunk ^ (row&3)
// GEMM1 stage: A 64x32 (4KB) | B 64x32 (4KB)   = 8KB;  3-stage ring = 24KB
// GEMM2 stage: A 128x32 (8KB) | B 128x32 (8KB) = 16KB; 4-stage ring = 64KB
#define G1_SA 0
#define G1_SB 4096
#define G1_ST 8192
#define G1_TOTAL (3 * G1_ST)
#define G2_SA 0
#define G2_SB 8192
#define G2_ST 16384
#define G2_TOTAL (4 * G2_ST)   // 65536 (needs MaxDynamicSharedMemorySize opt-in)

// ============================================================================
// Prep kernels (4x float4 per thread for deeper MLP).
// ============================================================================
#define N4G (N_EXP * 2 * I_DIM * H_DIM / 4)   // 4194304
#define N4D (N_EXP * H_DIM * I_DIM / 4)       // 2097152
#define N4X (T_TOK * H_DIM / 4)               // 262144
#define N4O (T_TOK * H_DIM / 4)               // 262144
#define P1_BLOCKS ((N4G + N4X) / 1024)        // 4352
#define P2_BLOCKS ((N4D + N4O) / 1024)        // 2304

__global__ void prep_gux(const float* __restrict__ gu,
                         const float* __restrict__ x,
                         const int*   __restrict__ idx,
                         const float* __restrict__ wts) {
    const int b = blockIdx.x;
    const int tid = threadIdx.x;

    if (b == P1_BLOCKS) {
        __shared__ int cnt[N_EXP];
        __shared__ int off[N_EXP];
        if (tid < N_EXP) cnt[tid] = 0;
        __syncthreads();
        #pragma unroll
        for (int j = 0; j < NPAIR / 256; j++)
            atomicAdd(&cnt[idx[tid + j * 256]], 1);
        __syncthreads();
        if (tid == 0) {
            int acc = 0;
            for (int e = 0; e < N_EXP; e++) { off[e] = acc; g_offset[e] = acc; acc += cnt[e]; }
            g_offset[N_EXP] = acc;
        }
        __syncthreads();
        if (tid < N_EXP) cnt[tid] = 0;
        __syncthreads();
        #pragma unroll
        for (int j = 0; j < NPAIR / 256; j++) {
            const int i = tid + j * 256;
            const int e = idx[i];
            const int pos = off[e] + atomicAdd(&cnt[e], 1);
            g_tok[pos] = i >> 2;
            g_wt[pos]  = wts[i];
        }
        return;
    }

    const int i = (b * 256 + tid) * 4;   // 4 float4s; N4G % 4 == 0 so no straddle
    const float* src;
    __half* hi;
    int j;
    if (i < N4G) { src = gu; j = i;       hi = g_GUh; }
    else         { src = x;  j = i - N4G; hi = g_Xh;  }
    #pragma unroll
    for (int q = 0; q < 4; q++) {
        float4 v = ((const float4*)src)[j + q];
        __half h0 = __float2half_rn(v.x), h1 = __float2half_rn(v.y);
        __half h2 = __float2half_rn(v.z), h3 = __float2half_rn(v.w);
        uint32_t hp0 = (uint32_t)__half_as_ushort(h0) | ((uint32_t)__half_as_ushort(h1) << 16);
        uint32_t hp1 = (uint32_t)__half_as_ushort(h2) | ((uint32_t)__half_as_ushort(h3) << 16);
        ((uint2*)hi)[j + q] = make_uint2(hp0, hp1);
    }
}

__global__ void prep_down(const float* __restrict__ dn, float* __restrict__ out) {
    const int tid = threadIdx.x;
    const int i = (blockIdx.x * 256 + tid) * 4;   // N4D % 4 == 0
    if (i < N4D) {
        #pragma unroll
        for (int q = 0; q < 4; q++) {
            float4 v = ((const float4*)dn)[i + q];
            __half h0 = __float2half_rn(v.x), h1 = __float2half_rn(v.y);
            __half h2 = __float2half_rn(v.z), h3 = __float2half_rn(v.w);
            uint32_t hp0 = (uint32_t)__half_as_ushort(h0) | ((uint32_t)__half_as_ushort(h1) << 16);
            uint32_t hp1 = (uint32_t)__half_as_ushort(h2) | ((uint32_t)__half_as_ushort(h3) << 16);
            ((uint2*)g_Dh)[i + q] = make_uint2(hp0, hp1);
        }
    } else {
        const int j = i - N4D;
        #pragma unroll
        for (int q = 0; q < 4; q++)
            ((float4*)out)[j + q] = make_float4(0.f, 0.f, 0.f, 0.f);
    }
}

// ============================================================================
// GEMM1 (R15 shape, unchanged): 64 pairs x 32 I-cols, K = 1024, 128 threads.
// ============================================================================
__global__ __launch_bounds__(128, 8) void gemm1_mma() {
    const int e     = blockIdx.z;
    const int start = g_offset[e];
    const int nrows = g_offset[e + 1] - start;
    const int row0  = blockIdx.y * 64;
    if (row0 >= nrows) return;
    const int col0 = blockIdx.x * 32;

    extern __shared__ char smem[];
    const uint32_t sbu = smem_to_u32(smem);
    const int tid  = threadIdx.x;
    const int wid  = tid >> 5, lane = tid & 31;
    const int g    = lane >> 2, tg = lane & 3;
    const int wm   = wid & 1, wn = wid >> 1;

    const int lr = tid >> 1;
    const int lc = (tid & 1) * 2;
    const bool v0 = (row0 + lr) < nrows;
    const int tok0 = v0 ? g_tok[start + row0 + lr] : 0;
    const __half* aptr = g_Xh + (size_t)tok0 * H_DIM;
    uint32_t soA[2];
    #pragma unroll
    for (int j = 0; j < 2; j++) soA[j] = (uint32_t)(lr * 64 + (((lc + j) ^ (lr & 3)) << 4));

    const size_t brow = ((size_t)e * 1024 + col0 + (lr >> 1) + (lr & 1) * 512) * H_DIM;

    const int quad = lane >> 3, lr8 = lane & 7;
    const int a_r  = wm * 32 + (quad & 1) * 8 + lr8;
    const int a_k8 = quad >> 1;
    const int b_rb = wn * 32 + (quad >> 1) * 8 + lr8;
    const int b_k8 = quad & 1;
    const uint32_t arx = (uint32_t)(a_r & 3);
    const uint32_t brx = (uint32_t)(b_rb & 3);
    uint32_t abase[2], bbase[2];
    #pragma unroll
    for (int mt = 0; mt < 2; mt++) abase[mt] = (uint32_t)((a_r + mt * 16) * 64);
    #pragma unroll
    for (int ntp = 0; ntp < 2; ntp++) bbase[ntp] = (uint32_t)((b_rb + ntp * 16) * 64);

    float acc[2][4][4];
    #pragma unroll
    for (int a = 0; a < 2; a++)
        #pragma unroll
        for (int b = 0; b < 4; b++)
            #pragma unroll
            for (int c = 0; c < 4; c++) acc[a][b][c] = 0.f;

    const int NCH = H_DIM / 32;   // 32
    #pragma unroll
    for (int s = 0; s < 2; s++) {
        uint32_t sb = sbu + s * G1_ST;
        #pragma unroll
        for (int j = 0; j < 2; j++) {
            cp16(sb + G1_SA + soA[j], aptr + s * 32 + (lc + j) * 8, v0 ? 16 : 0);
            cp16(sb + G1_SB + soA[j], g_GUh + brow + s * 32 + (lc + j) * 8, 16);
        }
        CP_COMMIT();
    }

    int cslot = 0, nslot = 2;
    #pragma unroll 1
    for (int ch = 0; ch < NCH; ch++) {
        CP_WAIT1();
        __syncthreads();
        {
            const int nc = ch + 2;
            if (nc < NCH) {
                uint32_t sb = sbu + nslot * G1_ST;
                #pragma unroll
                for (int j = 0; j < 2; j++) {
                    cp16(sb + G1_SA + soA[j], aptr + nc * 32 + (lc + j) * 8, v0 ? 16 : 0);
                    cp16(sb + G1_SB + soA[j], g_GUh + brow + nc * 32 + (lc + j) * 8, 16);
                }
            }
            CP_COMMIT();
        }
        const uint32_t st = sbu + cslot * G1_ST;
        #pragma unroll
        for (int kh8 = 0; kh8 < 4; kh8 += 2) {
            uint32_t Ah[2][4];
            #pragma unroll
            for (int mt = 0; mt < 2; mt++)
                ldsm_x4(Ah[mt], st + G1_SA + abase[mt] + ((((uint32_t)(kh8 + a_k8)) ^ arx) << 4));
            #pragma unroll
            for (int ntp = 0; ntp < 2; ntp++) {
                uint32_t Bh[4];
                ldsm_x4(Bh, st + G1_SB + bbase[ntp] + ((((uint32_t)(kh8 + b_k8)) ^ brx) << 4));
                #pragma unroll
                for (int mt = 0; mt < 2; mt++) {
                    mma16816(acc[mt][2 * ntp],     Ah[mt], Bh[0], Bh[1]);
                    mma16816(acc[mt][2 * ntp + 1], Ah[mt], Bh[2], Bh[3]);
                }
            }
        }
        cslot = (cslot == 2) ? 0 : cslot + 1;
        nslot = (nslot == 2) ? 0 : nslot + 1;
    }

    #pragma unroll
    for (int mt = 0; mt < 2; mt++) {
        #pragma unroll
        for (int nt = 0; nt < 4; nt++) {
            const int r  = wm * 32 + mt * 16 + g;
            const int jj = col0 + ((wn * 32 + nt * 8 + tg * 2) >> 1);
            const float* c = acc[mt][nt];
            #pragma unroll
            for (int hrow = 0; hrow < 2; hrow++) {
                const int rr = r + hrow * 8;
                if (row0 + rr < nrows) {
                    const float gate = c[hrow * 2], up = c[hrow * 2 + 1];
                    const float h = gate / (1.f + __expf(-gate)) * up;
                    g_Hh[(size_t)(start + row0 + rr) * I_DIM + jj] = __float2half_rn(h);
                }
            }
        }
    }
}

// ============================================================================
// GEMM2: 128 pairs x 128 H-cols, split-K x2, 256 threads, 4-stage ring.
// ============================================================================
__global__ __launch_bounds__(256, 3) void gemm2_mma(float* __restrict__ out) {
    const int e     = blockIdx.z >> 1;
    const int ks    = blockIdx.z & 1;
    const int start = g_offset[e];
    const int nrows = g_offset[e + 1] - start;
    const int row0  = blockIdx.y * 128;
    if (row0 >= nrows) return;
    const int col0 = blockIdx.x * 128;
    const int kofs = ks * 256;

    extern __shared__ char smem[];
    const uint32_t sbu = smem_to_u32(smem);
    const int tid  = threadIdx.x;
    const int wid  = tid >> 5, lane = tid & 31;
    const int g    = lane >> 2, tg = lane & 3;
    const int wm   = wid & 3, wn = wid >> 2;

    const int lr = tid >> 1;
    const int lc = (tid & 1) * 2;
    const bool v0 = (row0 + lr) < nrows;
    const size_t arow = (size_t)(start + row0 + (v0 ? lr : 0)) * I_DIM;
    const size_t brow = ((size_t)e * H_DIM + col0 + lr) * I_DIM;
    uint32_t so[2];
    #pragma unroll
    for (int j = 0; j < 2; j++) so[j] = (uint32_t)(lr * 64 + (((lc + j) ^ (lr & 3)) << 4));

    const int quad = lane >> 3, lr8 = lane & 7;
    const int a_r  = wm * 32 + (quad & 1) * 8 + lr8;
    const int a_k8 = quad >> 1;
    const int b_rb = wn * 64 + (quad >> 1) * 8 + lr8;
    const int b_k8 = quad & 1;
    const uint32_t arx = (uint32_t)(a_r & 3);
    const uint32_t brx = (uint32_t)(b_rb & 3);
    uint32_t abase[2], bbase[4];
    #pragma unroll
    for (int mt = 0; mt < 2; mt++) abase[mt] = (uint32_t)((a_r + mt * 16) * 64);
    #pragma unroll
    for (int ntp = 0; ntp < 4; ntp++) bbase[ntp] = (uint32_t)((b_rb + ntp * 16) * 64);

    float acc[2][8][4];
    #pragma unroll
    for (int a = 0; a < 2; a++)
        #pragma unroll
        for (int b = 0; b < 8; b++)
            #pragma unroll
            for (int c = 0; c < 4; c++) acc[a][b][c] = 0.f;

    const int NCH = 256 / 32;   // 8
    // prologue: issue stages 0..2
    #pragma unroll
    for (int s = 0; s < 3; s++) {
        uint32_t sb = sbu + s * G2_ST;
        #pragma unroll
        for (int j = 0; j < 2; j++) {
            const int eo = kofs + s * 32 + (lc + j) * 8;
            cp16(sb + G2_SA + so[j], g_Hh + arow + eo, v0 ? 16 : 0);
            cp16(sb + G2_SB + so[j], g_Dh + brow + eo, 16);
        }
        CP_COMMIT();
    }

    int cslot = 0, nslot = 3;
    #pragma unroll 1
    for (int ch = 0; ch < NCH; ch++) {
        CP_WAIT2();
        __syncthreads();
        {
            const int nc = ch + 3;
            if (nc < NCH) {
                uint32_t sb = sbu + nslot * G2_ST;
                #pragma unroll
                for (int j = 0; j < 2; j++) {
                    const int eo = kofs + nc * 32 + (lc + j) * 8;
                    cp16(sb + G2_SA + so[j], g_Hh + arow + eo, v0 ? 16 : 0);
                    cp16(sb + G2_SB + so[j], g_Dh + brow + eo, 16);
                }
            }
            CP_COMMIT();
        }
        const uint32_t st = sbu + cslot * G2_ST;
        #pragma unroll
        for (int kh8 = 0; kh8 < 4; kh8 += 2) {
            uint32_t Ah[2][4];
            #pragma unroll
            for (int mt = 0; mt < 2; mt++)
                ldsm_x4(Ah[mt], st + G2_SA + abase[mt] + ((((uint32_t)(kh8 + a_k8)) ^ arx) << 4));
            #pragma unroll
            for (int ntp = 0; ntp < 4; ntp++) {
                uint32_t Bh[4];
                ldsm_x4(Bh, st + G2_SB + bbase[ntp] + ((((uint32_t)(kh8 + b_k8)) ^ brx) << 4));
                #pragma unroll
                for (int mt = 0; mt < 2; mt++) {
                    mma16816(acc[mt][2 * ntp],     Ah[mt], Bh[0], Bh[1]);
                    mma16816(acc[mt][2 * ntp + 1], Ah[mt], Bh[2], Bh[3]);
                }
            }
        }
        cslot = (cslot + 1) & 3;
        nslot = (nslot + 1) & 3;
    }

    // Epilogue: weighted vectorized reduction into out[t, :]
    #pragma unroll
    for (int mt = 0; mt < 2; mt++) {
        #pragma unroll
        for (int hrow = 0; hrow < 2; hrow++) {
            const int rr = wm * 32 + mt * 16 + g + hrow * 8;
            if (row0 + rr < nrows) {
                const int pos = start + row0 + rr;
                const int t   = g_tok[pos];
                const float w = g_wt[pos];
                float* orow = out + (size_t)t * H_DIM;
                #pragma unroll
                for (int nt = 0; nt < 8; nt++) {
                    const int col = col0 + wn * 64 + nt * 8 + tg * 2;
                    red_add_v2(orow + col, w * acc[mt][nt][hrow * 2],
                                           w * acc[mt][nt][hrow * 2 + 1]);
                }
            }
        }
    }
}

// ============================================================================
// Launch (graph-capturable; R12-proven 2-stream fork/join)
// ============================================================================
extern "C" void kernel_launch(void* const* d_in, const int* in_sizes, int n_in,
                              void* d_out, int out_size)
{
    const float* hidden  = (const float*)d_in[0];
    const int*   idx     = (const int*)  d_in[1];
    const float* wts     = (const float*)d_in[2];
    const float* gate_up = (const float*)d_in[3];
    const float* down    = (const float*)d_in[4];
    float*       out     = (float*)d_out;

    static cudaStream_t s2 = nullptr;
    static cudaEvent_t evFork = nullptr, evJoin = nullptr;
    if (!s2) {
        cudaStreamCreateWithFlags(&s2, cudaStreamNonBlocking);
        cudaEventCreateWithFlags(&evFork, cudaEventDisableTiming);
        cudaEventCreateWithFlags(&evJoin, cudaEventDisableTiming);
        cudaFuncSetAttribute(gemm2_mma, cudaFuncAttributeMaxDynamicSharedMemorySize, G2_TOTAL);
    }

    // Fork side stream into the capture graph.
    cudaEventRecord(evFork, 0);
    cudaStreamWaitEvent(s2, evFork, 0);

    // Side stream: down conversion + output zeroing (needed only by gemm2).
    prep_down<<<P2_BLOCKS, 256, 0, s2>>>(down, out);
    cudaEventRecord(evJoin, s2);

    // Critical path: gate_up + hidden conversion + routing, then GEMM1.
    prep_gux<<<P1_BLOCKS + 1, 256>>>(gate_up, hidden, idx, wts);

    dim3 g1(I_DIM / 32, NPAIR / 64, N_EXP);         // (16, 64, 16)
    gemm1_mma<<<g1, 128, G1_TOTAL>>>();

    // Join before GEMM2 (needs g_Dh and zeroed out).
    cudaStreamWaitEvent(0, evJoin, 0);
    dim3 g2(H_DIM / 128, NPAIR / 128, N_EXP * 2);   // (8, 32, 32)
    gemm2_mma<<<g2, 256, G2_TOTAL>>>(out);
}